// round 4
// baseline (speedup 1.0000x reference)
#include <cuda_runtime.h>
#include <cuda_bf16.h>

// Problem shape (fixed by the reference): B=4, S=4096, D=1024.
#define BB   4
#define SS   4096
#define DD   1024
#define MQ   (BB * SS)          // 16384 rows for the fused [B*S, D] projections

// Scratch (allocation-free rule: __device__ globals).
__device__ float g_q[(long long)BB * SS * DD];   // 64 MB
__device__ float g_k[(long long)BB * SS * DD];   // 64 MB
__device__ float g_v[(long long)BB * SS * DD];   // 64 MB
__device__ float g_kv[(long long)BB * DD * DD];  // 16 MB

// ---------------------------------------------------------------------------
// Tiled SGEMM: C[M,N] = sum_k A(m,k) * B(k,n)  (+ bias[n] if BIAS)
//   AK  = true : A element (m,k) at A[m*lda + k]   (K contiguous)
//   AK  = false: A element (m,k) at A[k*lda + m]   (M contiguous)
//   BKC = true : B element (k,n) at B[n*ldb + k]   (K contiguous, i.e. B^T form)
//   BKC = false: B element (k,n) at B[k*ldb + n]   (N contiguous)
// blockIdx.z selects a batch via element strides sA/sB/sC.
// Requires: M%128==0, N%128==0, K%16==0, all tiles 16B-aligned (true here).
// ---------------------------------------------------------------------------
template <bool AK, bool BKC, bool BIAS>
__global__ void __launch_bounds__(256, 2)
sgemm_kernel(const float* __restrict__ A, const float* __restrict__ B,
             const float* __restrict__ bias, float* __restrict__ C,
             int M, int N, int K, int lda, int ldb,
             long long sA, long long sB, long long sC)
{
    A += (long long)blockIdx.z * sA;
    B += (long long)blockIdx.z * sB;
    C += (long long)blockIdx.z * sC;

    __shared__ float As[16][132];   // [k][m], +4 pad (132 % 4 == 0 keeps float4 align)
    __shared__ float Bs[16][132];   // [k][n]

    const int tid  = threadIdx.x;
    const int m0   = blockIdx.y * 128;
    const int n0   = blockIdx.x * 128;
    const int row0 = (tid >> 4) * 8;   // 0..120
    const int col0 = (tid & 15) * 8;   // 0..120

    float acc[8][8];
#pragma unroll
    for (int i = 0; i < 8; i++)
#pragma unroll
        for (int j = 0; j < 8; j++) acc[i][j] = 0.f;

    for (int k0 = 0; k0 < K; k0 += 16) {
        // ---- stage A tile into As[k][m] ----
        if (AK) {
            const int r  = tid >> 2;          // 0..63
            const int kc = (tid & 3) * 4;     // 0,4,8,12
#pragma unroll
            for (int i = 0; i < 2; i++) {
                const int row = r + i * 64;
                float4 t = *(const float4*)&A[(long long)(m0 + row) * lda + (k0 + kc)];
                As[kc + 0][row] = t.x;
                As[kc + 1][row] = t.y;
                As[kc + 2][row] = t.z;
                As[kc + 3][row] = t.w;
            }
        } else {
            const int kr = tid >> 5;          // 0..7
            const int c4 = (tid & 31) * 4;    // 0..124
#pragma unroll
            for (int i = 0; i < 2; i++) {
                float4 t = *(const float4*)&A[(long long)(k0 + kr + i * 8) * lda + (m0 + c4)];
                *(float4*)&As[kr + i * 8][c4] = t;
            }
        }
        // ---- stage B tile into Bs[k][n] ----
        if (BKC) {
            const int r  = tid >> 2;
            const int kc = (tid & 3) * 4;
#pragma unroll
            for (int i = 0; i < 2; i++) {
                const int row = r + i * 64;
                float4 t = *(const float4*)&B[(long long)(n0 + row) * ldb + (k0 + kc)];
                Bs[kc + 0][row] = t.x;
                Bs[kc + 1][row] = t.y;
                Bs[kc + 2][row] = t.z;
                Bs[kc + 3][row] = t.w;
            }
        } else {
            const int kr = tid >> 5;
            const int c4 = (tid & 31) * 4;
#pragma unroll
            for (int i = 0; i < 2; i++) {
                float4 t = *(const float4*)&B[(long long)(k0 + kr + i * 8) * ldb + (n0 + c4)];
                *(float4*)&Bs[kr + i * 8][c4] = t;
            }
        }
        __syncthreads();

        // ---- 8x8 microtile over 16 k-steps ----
#pragma unroll
        for (int kk = 0; kk < 16; kk++) {
            float a[8], b[8];
            *(float4*)&a[0] = *(const float4*)&As[kk][row0];
            *(float4*)&a[4] = *(const float4*)&As[kk][row0 + 4];
            *(float4*)&b[0] = *(const float4*)&Bs[kk][col0];
            *(float4*)&b[4] = *(const float4*)&Bs[kk][col0 + 4];
#pragma unroll
            for (int i = 0; i < 8; i++)
#pragma unroll
                for (int j = 0; j < 8; j++)
                    acc[i][j] = fmaf(a[i], b[j], acc[i][j]);
        }
        __syncthreads();
    }

    float bv[8];
#pragma unroll
    for (int j = 0; j < 8; j++) bv[j] = BIAS ? bias[n0 + col0 + j] : 0.f;

#pragma unroll
    for (int i = 0; i < 8; i++) {
        const long long crow = (long long)(m0 + row0 + i) * N + (n0 + col0);
        float4 o0 = make_float4(acc[i][0] + bv[0], acc[i][1] + bv[1],
                                acc[i][2] + bv[2], acc[i][3] + bv[3]);
        float4 o1 = make_float4(acc[i][4] + bv[4], acc[i][5] + bv[5],
                                acc[i][6] + bv[6], acc[i][7] + bv[7]);
        *(float4*)&C[crow]     = o0;
        *(float4*)&C[crow + 4] = o1;
    }
}

// ---------------------------------------------------------------------------
// Row softmax (q): softmax over last dim D=1024. One block (256 thr) per row.
// ---------------------------------------------------------------------------
__global__ void row_softmax_kernel(float* __restrict__ x)
{
    const long long row = blockIdx.x;
    float* p = x + row * DD;
    const int t = threadIdx.x;

    float v[4];
#pragma unroll
    for (int i = 0; i < 4; i++) v[i] = p[t + i * 256];

    float m = fmaxf(fmaxf(v[0], v[1]), fmaxf(v[2], v[3]));
#pragma unroll
    for (int o = 16; o; o >>= 1) m = fmaxf(m, __shfl_xor_sync(0xffffffffu, m, o));

    __shared__ float redm[8];
    __shared__ float reds[8];
    if ((t & 31) == 0) redm[t >> 5] = m;
    __syncthreads();
    m = redm[0];
#pragma unroll
    for (int i = 1; i < 8; i++) m = fmaxf(m, redm[i]);

    float s = 0.f;
#pragma unroll
    for (int i = 0; i < 4; i++) { v[i] = __expf(v[i] - m); s += v[i]; }
#pragma unroll
    for (int o = 16; o; o >>= 1) s += __shfl_xor_sync(0xffffffffu, s, o);
    if ((t & 31) == 0) reds[t >> 5] = s;
    __syncthreads();
    s = 0.f;
#pragma unroll
    for (int i = 0; i < 8; i++) s += reds[i];
    const float inv = 1.f / s;
#pragma unroll
    for (int i = 0; i < 4; i++) p[t + i * 256] = v[i] * inv;
}

// ---------------------------------------------------------------------------
// Column softmax (k, v): softmax over S=4096 per (b, d) column, then *scale.
// grid (D/32, B), block (32, 8). Online max/sum pass + write pass (2R + 1W).
// Consecutive threadIdx.x -> consecutive columns -> coalesced.
// ---------------------------------------------------------------------------
__global__ void col_softmax_kernel(float* __restrict__ x, float scale)
{
    const int tx = threadIdx.x;
    const int ty = threadIdx.y;
    const int c  = blockIdx.x * 32 + tx;
    float* p = x + (long long)blockIdx.y * SS * DD + c;

    float m = -3.4e38f, s = 0.f;
    for (int r = ty; r < SS; r += 8) {
        const float xv = p[(long long)r * DD];
        if (xv > m) { s *= __expf(m - xv); m = xv; }
        s += __expf(xv - m);
    }

    __shared__ float sm[8][32];
    __shared__ float ssum[8][32];
    sm[ty][tx] = m;
    ssum[ty][tx] = s;
    __syncthreads();

    if (ty == 0) {
        float M = sm[0][tx];
#pragma unroll
        for (int i = 1; i < 8; i++) M = fmaxf(M, sm[i][tx]);
        float T = 0.f;
#pragma unroll
        for (int i = 0; i < 8; i++) T += ssum[i][tx] * __expf(sm[i][tx] - M);
        sm[0][tx]   = M;
        ssum[0][tx] = scale / T;
    }
    __syncthreads();

    const float M = sm[0][tx];
    const float R = ssum[0][tx];
    for (int r = ty; r < SS; r += 8) {
        const long long idx = (long long)r * DD;
        p[idx] = __expf(p[idx] - M) * R;
    }
}

// ---------------------------------------------------------------------------
// launch
// ---------------------------------------------------------------------------
extern "C" void kernel_launch(void* const* d_in, const int* in_sizes, int n_in,
                              void* d_out, int out_size)
{
    const float* h  = (const float*)d_in[0];
    const float* Wq = (const float*)d_in[1];
    const float* bq = (const float*)d_in[2];
    const float* Wk = (const float*)d_in[3];
    const float* bk = (const float*)d_in[4];
    const float* Wv = (const float*)d_in[5];
    const float* bv = (const float*)d_in[6];
    float* out = (float*)d_out;

    float *q, *k, *v, *kv;
    cudaGetSymbolAddress((void**)&q,  g_q);
    cudaGetSymbolAddress((void**)&k,  g_k);
    cudaGetSymbolAddress((void**)&v,  g_v);
    cudaGetSymbolAddress((void**)&kv, g_kv);

    const dim3 blk(256);
    const long long sQKV = (long long)SS * DD;   // per-batch stride in q/k/v/out
    const long long sKV  = (long long)DD * DD;   // per-batch stride in KV

    // 1) Projections: [16384,1024] = h[16384,1024] @ W^T[1024,1024] + b
    {
        dim3 g(DD / 128, MQ / 128, 1);
        sgemm_kernel<true, true, true><<<g, blk>>>(h, Wq, bq, q, MQ, DD, DD, DD, DD, 0, 0, 0);
        sgemm_kernel<true, true, true><<<g, blk>>>(h, Wk, bk, k, MQ, DD, DD, DD, DD, 0, 0, 0);
        sgemm_kernel<true, true, true><<<g, blk>>>(h, Wv, bv, v, MQ, DD, DD, DD, DD, 0, 0, 0);
    }

    // 2) Softmaxes
    row_softmax_kernel<<<MQ, 256>>>(q);                                   // over D
    col_softmax_kernel<<<dim3(DD / 32, BB), dim3(32, 8)>>>(k, 1.0f / 32.0f); // over S, *1/sqrt(D)
    col_softmax_kernel<<<dim3(DD / 32, BB), dim3(32, 8)>>>(v, 1.0f);         // over S

    // 3) KV[b] = k[b]^T @ v[b]  : M=N=1024, K=4096 (both operands M/N-contiguous)
    sgemm_kernel<false, false, false><<<dim3(DD / 128, DD / 128, BB), blk>>>(
        k, v, nullptr, kv, DD, DD, SS, DD, DD, sQKV, sQKV, sKV);

    // 4) out[b] = q[b] @ KV[b] : M=4096, N=1024, K=1024
    sgemm_kernel<true, false, false><<<dim3(DD / 128, SS / 128, BB), blk>>>(
        q, kv, nullptr, out, SS, DD, DD, DD, DD, sQKV, sKV, sQKV);
}

// round 6
// speedup vs baseline: 2.7777x; 2.7777x over previous
#include <cuda_runtime.h>
#include <cuda_bf16.h>
#include <cstdint>

// Shapes fixed by the reference: B=4, S=4096, D=1024.
#define BB 4
#define SS 4096
#define DD 1024
#define MQ (BB * SS)     // 16384

// ---------------------------------------------------------------------------
// Device scratch (allocation-free rule)
// ---------------------------------------------------------------------------
__device__ float          g_q [(long long)MQ * DD];          // fp32 q logits
__device__ float          g_k [(long long)MQ * DD];
__device__ float          g_v [(long long)MQ * DD];
__device__ __nv_bfloat16  g_h2[(long long)MQ * 2048];        // [H_hi | H_lo]
__device__ __nv_bfloat16  g_w3[(long long)3 * DD * 3072];    // [W_hi | W_lo | W_hi] x3
__device__ __nv_bfloat16  g_qb[(long long)MQ * DD];          // q probs bf16
__device__ __nv_bfloat16  g_kT[(long long)BB * DD * SS];     // k^T per batch [D,S]
__device__ __nv_bfloat16  g_vT[(long long)BB * DD * SS];
__device__ __nv_bfloat16  g_kvt[(long long)BB * DD * DD];    // KVT[a,c] = sum_s v[s,a]k[s,c]

// ---------------------------------------------------------------------------
// PTX helpers — all baseline compute_100-legal (sm_80+ ISA): no tcgen05.
// ---------------------------------------------------------------------------
__device__ __forceinline__ uint32_t smem_u32(const void* p) {
    uint32_t a;
    asm("{ .reg .u64 t; cvta.to.shared.u64 t, %1; cvt.u32.u64 %0, t; }" : "=r"(a) : "l"(p));
    return a;
}
#define CP_ASYNC16(dst, src) \
    asm volatile("cp.async.cg.shared.global [%0], [%1], 16;" :: "r"(dst), "l"(src) : "memory")
#define CP_COMMIT() asm volatile("cp.async.commit_group;" ::: "memory")
#define CP_WAIT1()  asm volatile("cp.async.wait_group 1;" ::: "memory")

__device__ __forceinline__ void ldsm_x4(uint32_t (&r)[4], uint32_t addr) {
    asm volatile("ldmatrix.sync.aligned.m8n8.x4.shared.b16 {%0,%1,%2,%3}, [%4];"
                 : "=r"(r[0]), "=r"(r[1]), "=r"(r[2]), "=r"(r[3]) : "r"(addr));
}
__device__ __forceinline__ void mma16816(float* c, const uint32_t* a, uint32_t b0, uint32_t b1) {
    asm volatile("mma.sync.aligned.m16n8k16.row.col.f32.bf16.bf16.f32 "
                 "{%0,%1,%2,%3}, {%4,%5,%6,%7}, {%8,%9}, {%0,%1,%2,%3};"
                 : "+f"(c[0]), "+f"(c[1]), "+f"(c[2]), "+f"(c[3])
                 : "r"(a[0]), "r"(a[1]), "r"(a[2]), "r"(a[3]), "r"(b0), "r"(b1));
}
// SW64 swizzle for 64-byte rows (BK=32 bf16): bits[4:5] ^= bits[7:8].
__device__ __forceinline__ uint32_t swz(uint32_t byte_off) {
    return byte_off ^ ((byte_off >> 3) & 0x30u);
}

struct EpiArgs {
    void* c0; void* c1; void* c2;
    const float* b0; const float* b1; const float* b2;
};
struct W3Args { const float* w0; const float* w1; const float* w2; };

// ---------------------------------------------------------------------------
// bf16 HMMA GEMM (mma.sync), 3-stage cp.async pipeline.
//   C[M,N] = A[M,K](K-major,lda) @ B[N,K](K-major,ldb)^T
//   CTA tile 128x128x32; 8 warps (2M x 4N), warp tile 64x32.
//   REMAP: logical k>=1024 maps to A column k-1024 (split-bf16 trick)
//   P3   : 3-way output routing by n/1024 (fused q/k/v projection), fp32+bias
//   OBF16: bf16 output; else fp32 output.
// Requires M%128==0, N%128==0, K%32==0.
// ---------------------------------------------------------------------------
template <bool REMAP, bool P3, bool OBF16>
__global__ void __launch_bounds__(256, 2)
gemm_mma(const __nv_bfloat16* __restrict__ A, int lda,
         const __nv_bfloat16* __restrict__ B, int ldb,
         EpiArgs ep, int ldc, int K,
         long long sA, long long sB, long long sC)
{
    __shared__ __align__(1024) char smem[3 * 16384];  // per stage: A 8KB + B 8KB

    const int tid = threadIdx.x;
    const int bz  = blockIdx.z;
    A += (long long)bz * sA;
    B += (long long)bz * sB;

    const int m0 = blockIdx.y * 128;
    const int n0 = blockIdx.x * 128;

    const int wid  = tid >> 5;
    const int lane = tid & 31;
    const int wm   = wid >> 2;        // 0..1  (M warp)
    const int wn   = wid & 3;         // 0..3  (N warp)
    const int fr   = lane & 15;       // ldmatrix row-within-16
    const int kc   = lane >> 4;       // ldmatrix k-chunk (0/1)

    // g2s mapping: chunk c = tid&3 (16B within 64B row), row r = tid>>2 (+64)
    const int lr = tid >> 2;
    const int lc = tid & 3;

    const uint32_t sm_base = smem_u32(smem);

    auto issue = [&](int kt) {
        const int k0  = kt * 32;
        const int ak0 = REMAP ? (k0 >= 1024 ? k0 - 1024 : k0) : k0;
        const int st  = kt % 3;
        const uint32_t sa = sm_base + st * 16384;
        const uint32_t sb = sa + 8192;
#pragma unroll
        for (int i = 0; i < 2; i++) {
            const int r = lr + i * 64;
            const uint32_t off = swz((uint32_t)(r * 64 + lc * 16));
            CP_ASYNC16(sa + off, A + (size_t)(m0 + r) * lda + ak0 + lc * 8);
            CP_ASYNC16(sb + off, B + (size_t)(n0 + r) * ldb + k0  + lc * 8);
        }
        CP_COMMIT();
    };

    float acc[4][4][4];
#pragma unroll
    for (int mi = 0; mi < 4; mi++)
#pragma unroll
        for (int nj = 0; nj < 4; nj++)
#pragma unroll
            for (int d = 0; d < 4; d++) acc[mi][nj][d] = 0.f;

    const int KT = K / 32;
    issue(0);
    issue(1);

    for (int kt = 0; kt < KT; ++kt) {
        CP_WAIT1();          // group kt complete
        __syncthreads();     // data visible; also protects buf reuse
        if (kt + 2 < KT) issue(kt + 2);

        const int st = kt % 3;
        const uint32_t sa = sm_base + st * 16384;
        const uint32_t sb = sa + 8192;

#pragma unroll
        for (int ks = 0; ks < 2; ks++) {
            uint32_t af[4][4];
#pragma unroll
            for (int mi = 0; mi < 4; mi++) {
                const uint32_t off =
                    swz((uint32_t)((wm * 64 + mi * 16 + fr) * 64 + ks * 32 + kc * 16));
                ldsm_x4(af[mi], sa + off);
            }
            uint32_t bf[2][4];
#pragma unroll
            for (int nj2 = 0; nj2 < 2; nj2++) {
                const uint32_t off =
                    swz((uint32_t)((wn * 32 + nj2 * 16 + fr) * 64 + ks * 32 + kc * 16));
                ldsm_x4(bf[nj2], sb + off);
            }
#pragma unroll
            for (int mi = 0; mi < 4; mi++)
#pragma unroll
                for (int nj = 0; nj < 4; nj++)
                    mma16816(acc[mi][nj], af[mi],
                             bf[nj >> 1][nj & 1], bf[nj >> 1][(nj & 1) + 2]);
        }
    }

    // ---- epilogue ----
    const int qr = lane >> 2;          // 0..7
    const int qc = (lane & 3) * 2;     // 0,2,4,6

    if (P3) {
        const int oi = n0 >> 10;
        float* Cp        = (oi == 0) ? (float*)ep.c0 : (oi == 1) ? (float*)ep.c1 : (float*)ep.c2;
        const float* bp  = (oi == 0) ? ep.b0 : (oi == 1) ? ep.b1 : ep.b2;
        const int nb = n0 & 1023;
#pragma unroll
        for (int mi = 0; mi < 4; mi++) {
#pragma unroll
            for (int nj = 0; nj < 4; nj++) {
                const int gm = m0 + wm * 64 + mi * 16 + qr;
                const int nn = nb + wn * 32 + nj * 8 + qc;
                const float b0 = bp[nn], b1 = bp[nn + 1];
                float* p0 = Cp + (size_t)gm * ldc + nn;
                float* p1 = Cp + (size_t)(gm + 8) * ldc + nn;
                *(float2*)p0 = make_float2(acc[mi][nj][0] + b0, acc[mi][nj][1] + b1);
                *(float2*)p1 = make_float2(acc[mi][nj][2] + b0, acc[mi][nj][3] + b1);
            }
        }
    } else if (OBF16) {
        __nv_bfloat16* Cp = (__nv_bfloat16*)ep.c0 + (long long)bz * sC;
#pragma unroll
        for (int mi = 0; mi < 4; mi++) {
#pragma unroll
            for (int nj = 0; nj < 4; nj++) {
                const int gm = m0 + wm * 64 + mi * 16 + qr;
                const int gn = n0 + wn * 32 + nj * 8 + qc;
                *(__nv_bfloat162*)(Cp + (size_t)gm * ldc + gn) =
                    __floats2bfloat162_rn(acc[mi][nj][0], acc[mi][nj][1]);
                *(__nv_bfloat162*)(Cp + (size_t)(gm + 8) * ldc + gn) =
                    __floats2bfloat162_rn(acc[mi][nj][2], acc[mi][nj][3]);
            }
        }
    } else {
        float* Cp = (float*)ep.c0 + (long long)bz * sC;
#pragma unroll
        for (int mi = 0; mi < 4; mi++) {
#pragma unroll
            for (int nj = 0; nj < 4; nj++) {
                const int gm = m0 + wm * 64 + mi * 16 + qr;
                const int gn = n0 + wn * 32 + nj * 8 + qc;
                *(float2*)(Cp + (size_t)gm * ldc + gn) =
                    make_float2(acc[mi][nj][0], acc[mi][nj][1]);
                *(float2*)(Cp + (size_t)(gm + 8) * ldc + gn) =
                    make_float2(acc[mi][nj][2], acc[mi][nj][3]);
            }
        }
    }
}

// ---------------------------------------------------------------------------
// conv_h: h fp32 [MQ,1024] -> H2 bf16 [MQ, 2048] = [hi | lo]
// ---------------------------------------------------------------------------
__global__ void conv_h_kernel(const float* __restrict__ h, __nv_bfloat16* __restrict__ h2)
{
    const size_t gid = (size_t)blockIdx.x * 256 + threadIdx.x;
    const size_t idx = gid * 4;
    const size_t rr  = idx >> 10;
    const size_t cc  = idx & 1023;
    float4 x = *(const float4*)(h + idx);
    __nv_bfloat16 hi[4], lo[4];
    const float xs[4] = { x.x, x.y, x.z, x.w };
#pragma unroll
    for (int i = 0; i < 4; i++) {
        hi[i] = __float2bfloat16(xs[i]);
        lo[i] = __float2bfloat16(xs[i] - __bfloat162float(hi[i]));
    }
    *(uint2*)(h2 + rr * 2048 + cc)        = *(const uint2*)hi;
    *(uint2*)(h2 + rr * 2048 + 1024 + cc) = *(const uint2*)lo;
}

// conv_w: 3 weights fp32 [1024,1024] -> W3 bf16 [3*1024, 3072] = [hi | lo | hi]
__global__ void conv_w_kernel(W3Args w, __nv_bfloat16* __restrict__ w3)
{
    const size_t gid = (size_t)blockIdx.x * 256 + threadIdx.x;
    const size_t idx = gid * 4;
    const int    oi  = (int)(idx >> 20);
    const size_t rem = idx & 1048575;
    const size_t n   = rem >> 10;
    const size_t cc  = rem & 1023;
    const float* W = (oi == 0) ? w.w0 : (oi == 1) ? w.w1 : w.w2;
    float4 x = *(const float4*)(W + rem);
    __nv_bfloat16 hi[4], lo[4];
    const float xs[4] = { x.x, x.y, x.z, x.w };
#pragma unroll
    for (int i = 0; i < 4; i++) {
        hi[i] = __float2bfloat16(xs[i]);
        lo[i] = __float2bfloat16(xs[i] - __bfloat162float(hi[i]));
    }
    __nv_bfloat16* row = w3 + ((size_t)oi * 1024 + n) * 3072;
    *(uint2*)(row + cc)        = *(const uint2*)hi;
    *(uint2*)(row + 1024 + cc) = *(const uint2*)lo;
    *(uint2*)(row + 2048 + cc) = *(const uint2*)hi;
}

// ---------------------------------------------------------------------------
// Row softmax (q) over D=1024, fp32 in -> bf16 out. One block per row.
// ---------------------------------------------------------------------------
__global__ void row_softmax_kernel(const float* __restrict__ x, __nv_bfloat16* __restrict__ o)
{
    const long long row = blockIdx.x;
    const float* p = x + row * DD;
    __nv_bfloat16* q = o + row * DD;
    const int t = threadIdx.x;

    float v[4];
#pragma unroll
    for (int i = 0; i < 4; i++) v[i] = p[t + i * 256];

    float m = fmaxf(fmaxf(v[0], v[1]), fmaxf(v[2], v[3]));
#pragma unroll
    for (int off = 16; off; off >>= 1) m = fmaxf(m, __shfl_xor_sync(0xffffffffu, m, off));

    __shared__ float redm[8], reds[8];
    if ((t & 31) == 0) redm[t >> 5] = m;
    __syncthreads();
    m = redm[0];
#pragma unroll
    for (int i = 1; i < 8; i++) m = fmaxf(m, redm[i]);

    float s = 0.f;
#pragma unroll
    for (int i = 0; i < 4; i++) { v[i] = __expf(v[i] - m); s += v[i]; }
#pragma unroll
    for (int off = 16; off; off >>= 1) s += __shfl_xor_sync(0xffffffffu, s, off);
    if ((t & 31) == 0) reds[t >> 5] = s;
    __syncthreads();
    s = 0.f;
#pragma unroll
    for (int i = 0; i < 8; i++) s += reds[i];
    const float inv = 1.f / s;
#pragma unroll
    for (int i = 0; i < 4; i++) q[t + i * 256] = __float2bfloat16(v[i] * inv);
}

// ---------------------------------------------------------------------------
// Column softmax over S=4096 + scale, fused transpose + bf16:
//   in : fp32 [S, D] (per batch), out : bf16 [D, S] (per batch)
// grid (D/32, B), block (32, 8).
// ---------------------------------------------------------------------------
__global__ void col_softmaxT_kernel(const float* __restrict__ x,
                                    __nv_bfloat16* __restrict__ xT, float scale)
{
    const int tx = threadIdx.x;
    const int ty = threadIdx.y;
    const int d0 = blockIdx.x * 32;
    const float* base = x + (long long)blockIdx.y * SS * DD;
    __nv_bfloat16* ob = xT + (long long)blockIdx.y * DD * SS + (long long)d0 * SS;
    const float* p = base + d0 + tx;

    float m = -3.4e38f, s = 0.f;
    for (int r = ty; r < SS; r += 8) {
        const float xv = p[(long long)r * DD];
        if (xv > m) { s *= __expf(m - xv); m = xv; }
        s += __expf(xv - m);
    }
    __shared__ float sm[8][32], ssum[8][32];
    sm[ty][tx] = m; ssum[ty][tx] = s;
    __syncthreads();
    __shared__ float colM[32], colR[32];
    if (ty == 0) {
        float M = sm[0][tx];
#pragma unroll
        for (int i = 1; i < 8; i++) M = fmaxf(M, sm[i][tx]);
        float T = 0.f;
#pragma unroll
        for (int i = 0; i < 8; i++) T += ssum[i][tx] * __expf(sm[i][tx] - M);
        colM[tx] = M; colR[tx] = scale / T;
    }
    __syncthreads();
    const float M = colM[tx];
    const float R = colR[tx];

    __shared__ float tile[32][33];
    for (int s0 = 0; s0 < SS; s0 += 32) {
#pragma unroll
        for (int j = 0; j < 4; j++) {
            const int sl = ty + 8 * j;
            tile[sl][tx] = __expf(p[(long long)(s0 + sl) * DD] - M) * R;
        }
        __syncthreads();
#pragma unroll
        for (int j = 0; j < 4; j++) {
            const int dl = ty + 8 * j;
            ob[(long long)dl * SS + s0 + tx] = __float2bfloat16(tile[tx][dl]);
        }
        __syncthreads();
    }
}

// ---------------------------------------------------------------------------
// launch
// ---------------------------------------------------------------------------
extern "C" void kernel_launch(void* const* d_in, const int* in_sizes, int n_in,
                              void* d_out, int out_size)
{
    const float* h  = (const float*)d_in[0];
    const float* Wq = (const float*)d_in[1];
    const float* bq = (const float*)d_in[2];
    const float* Wk = (const float*)d_in[3];
    const float* bk = (const float*)d_in[4];
    const float* Wv = (const float*)d_in[5];
    const float* bv = (const float*)d_in[6];
    float* out = (float*)d_out;

    float *q, *k, *v;
    __nv_bfloat16 *h2, *w3, *qb, *kT, *vT, *kvt;
    cudaGetSymbolAddress((void**)&q,   g_q);
    cudaGetSymbolAddress((void**)&k,   g_k);
    cudaGetSymbolAddress((void**)&v,   g_v);
    cudaGetSymbolAddress((void**)&h2,  g_h2);
    cudaGetSymbolAddress((void**)&w3,  g_w3);
    cudaGetSymbolAddress((void**)&qb,  g_qb);
    cudaGetSymbolAddress((void**)&kT,  g_kT);
    cudaGetSymbolAddress((void**)&vT,  g_vT);
    cudaGetSymbolAddress((void**)&kvt, g_kvt);

    // 1) split-bf16 conversions
    conv_h_kernel<<<MQ * DD / 1024, 256>>>(h, h2);
    W3Args wa{ Wq, Wk, Wv };
    conv_w_kernel<<<3 * DD * DD / 1024, 256>>>(wa, w3);

    // 2) fused projection GEMM: [16384, 3072] = H' @ W3^T  (K=3072 split-bf16)
    //    output cols [0,1024)->q, [1024,2048)->k, [2048,3072)->v (fp32 + bias)
    {
        EpiArgs ep{ q, k, v, bq, bk, bv };
        gemm_mma<true, true, false><<<dim3(24, 128, 1), 256>>>(
            h2, 2048, w3, 3072, ep, 1024, 3072, 0, 0, 0);
    }

    // 3) softmaxes (fused convert / transpose to bf16)
    row_softmax_kernel<<<MQ, 256>>>(q, qb);
    col_softmaxT_kernel<<<dim3(DD / 32, BB), dim3(32, 8)>>>(k, kT, 1.0f / 32.0f);
    col_softmaxT_kernel<<<dim3(DD / 32, BB), dim3(32, 8)>>>(v, vT, 1.0f);

    // 4) KVT[b][a,c] = sum_s vT[b][a,s] * kT[b][c,s]   (M=N=1024, K=4096, bf16 out)
    {
        EpiArgs ep{ kvt, nullptr, nullptr, nullptr, nullptr, nullptr };
        gemm_mma<false, false, true><<<dim3(8, 8, BB), 256>>>(
            vT, SS, kT, SS, ep, DD, SS,
            (long long)DD * SS, (long long)DD * SS, (long long)DD * DD);
    }

    // 5) out[b] = qb[b] @ KVT[b]^T  (both K-major over the 1024 contraction dim)
    {
        EpiArgs ep{ out, nullptr, nullptr, nullptr, nullptr, nullptr };
        gemm_mma<false, false, false><<<dim3(8, 32, BB), 256>>>(
            qb, DD, kvt, DD, ep, DD, DD,
            (long long)SS * DD, (long long)DD * DD, (long long)SS * DD);
    }
}

// round 8
// speedup vs baseline: 4.5116x; 1.6243x over previous
#include <cuda_runtime.h>
#include <cuda_fp16.h>
#include <cstdint>

// Shapes fixed by the reference: B=4, S=4096, D=1024.
#define BB 4
#define SS 4096
#define DD 1024
#define MQ (BB * SS)     // 16384

// Scaling: q' = q*2^8, k' = softmax_k*2^8 (1/sqrt(D)=1/32 folded into final),
// v' = v*2^8.  kvt' = 2^21 * KVT_true.  out = q'*kvt'^T * 2^-29 (exact pow2,
// includes the 1/32).
#define OUT_SCALE (1.0f / 536870912.0f)   // 2^-29
#define PROB_SCALE 256.0f

// ---------------------------------------------------------------------------
// Device scratch (allocation-free rule)
// ---------------------------------------------------------------------------
__device__ float  g_q [(long long)MQ * DD];           // fp32 q logits
__device__ float  g_k [(long long)MQ * DD];
__device__ float  g_v [(long long)MQ * DD];
__device__ __half g_hh[(long long)MQ * DD];           // h fp16
__device__ __half g_w3[(long long)3 * DD * DD];       // [Wq;Wk;Wv] fp16, rows=3072
__device__ __half g_qb[(long long)MQ * DD];           // q' fp16
__device__ __half g_kT[(long long)BB * DD * SS];      // k'^T per batch [D,S]
__device__ __half g_vT[(long long)BB * DD * SS];
__device__ __half g_kvt[(long long)BB * DD * DD];     // kvt'[a,c]

// ---------------------------------------------------------------------------
// PTX helpers (baseline sm_80+ ISA — safe through compute_100 lowering)
// ---------------------------------------------------------------------------
__device__ __forceinline__ uint32_t smem_u32(const void* p) {
    uint32_t a;
    asm("{ .reg .u64 t; cvta.to.shared.u64 t, %1; cvt.u32.u64 %0, t; }" : "=r"(a) : "l"(p));
    return a;
}
#define CP_ASYNC16(dst, src) \
    asm volatile("cp.async.cg.shared.global [%0], [%1], 16;" :: "r"(dst), "l"(src) : "memory")
#define CP_COMMIT() asm volatile("cp.async.commit_group;" ::: "memory")
#define CP_WAIT1()  asm volatile("cp.async.wait_group 1;" ::: "memory")

__device__ __forceinline__ void ldsm_x4(uint32_t (&r)[4], uint32_t addr) {
    asm volatile("ldmatrix.sync.aligned.m8n8.x4.shared.b16 {%0,%1,%2,%3}, [%4];"
                 : "=r"(r[0]), "=r"(r[1]), "=r"(r[2]), "=r"(r[3]) : "r"(addr));
}
__device__ __forceinline__ void mma16816(float* c, const uint32_t* a, uint32_t b0, uint32_t b1) {
    asm volatile("mma.sync.aligned.m16n8k16.row.col.f32.f16.f16.f32 "
                 "{%0,%1,%2,%3}, {%4,%5,%6,%7}, {%8,%9}, {%0,%1,%2,%3};"
                 : "+f"(c[0]), "+f"(c[1]), "+f"(c[2]), "+f"(c[3])
                 : "r"(a[0]), "r"(a[1]), "r"(a[2]), "r"(a[3]), "r"(b0), "r"(b1));
}
// SW64 swizzle for 64-byte rows (BK=32 halves): bits[4:5] ^= bits[7:8].
__device__ __forceinline__ uint32_t swz(uint32_t byte_off) {
    return byte_off ^ ((byte_off >> 3) & 0x30u);
}

struct EpiArgs {
    void* c0; void* c1; void* c2;
    const float* b0; const float* b1; const float* b2;
    float oscale;
};
struct W3Args { const float* w0; const float* w1; const float* w2; };

// ---------------------------------------------------------------------------
// fp16 HMMA GEMM (mma.sync), 3-stage cp.async pipeline (48KB static smem).
//   C[M,N] = A[M,K](K-major,lda) @ B[N,K](K-major,ldb)^T
//   CTA tile 128x128x32; 8 warps (2M x 4N), warp tile 64x32.
//   P3   : 3-way output routing by n/1024 (fused q/k/v projection), fp32+bias
//   OHALF: fp16 output; else fp32 output scaled by ep.oscale.
// Requires M%128==0, N%128==0, K%32==0, K/32 >= 2.
// ---------------------------------------------------------------------------
template <bool P3, bool OHALF>
__global__ void __launch_bounds__(256, 2)
gemm_mma(const __half* __restrict__ A, int lda,
         const __half* __restrict__ B, int ldb,
         EpiArgs ep, int ldc, int K,
         long long sA, long long sB, long long sC)
{
    __shared__ __align__(1024) char smem[3 * 16384];  // per stage: A 8KB + B 8KB

    const int tid = threadIdx.x;
    const int bz  = blockIdx.z;
    A += (long long)bz * sA;
    B += (long long)bz * sB;

    const int m0 = blockIdx.y * 128;
    const int n0 = blockIdx.x * 128;

    const int wid  = tid >> 5;
    const int lane = tid & 31;
    const int wm   = wid >> 2;        // 0..1  (M warp)
    const int wn   = wid & 3;         // 0..3  (N warp)
    const int fr   = lane & 15;       // ldmatrix row-within-16
    const int kc   = lane >> 4;       // ldmatrix k-chunk (0/1)

    const int lr = tid >> 2;          // g2s row (+64)
    const int lc = tid & 3;           // g2s 16B chunk within 64B row

    const uint32_t sm_base = smem_u32(smem);

    auto issue = [&](int kt) {
        const int k0 = kt * 32;
        const int st = kt % 3;
        const uint32_t sa = sm_base + st * 16384;
        const uint32_t sb = sa + 8192;
#pragma unroll
        for (int i = 0; i < 2; i++) {
            const int r = lr + i * 64;
            const uint32_t off = swz((uint32_t)(r * 64 + lc * 16));
            CP_ASYNC16(sa + off, A + (size_t)(m0 + r) * lda + k0 + lc * 8);
            CP_ASYNC16(sb + off, B + (size_t)(n0 + r) * ldb + k0 + lc * 8);
        }
        CP_COMMIT();
    };

    float acc[4][4][4];
#pragma unroll
    for (int mi = 0; mi < 4; mi++)
#pragma unroll
        for (int nj = 0; nj < 4; nj++)
#pragma unroll
            for (int d = 0; d < 4; d++) acc[mi][nj][d] = 0.f;

    const int KT = K / 32;
    issue(0);
    issue(1);

    for (int kt = 0; kt < KT; ++kt) {
        CP_WAIT1();          // group kt complete (<=1 group still pending)
        __syncthreads();     // data visible; all warps done with prior stage
        if (kt + 2 < KT) issue(kt + 2);

        const int st = kt % 3;
        const uint32_t sa = sm_base + st * 16384;
        const uint32_t sb = sa + 8192;

#pragma unroll
        for (int ks = 0; ks < 2; ks++) {
            uint32_t af[4][4];
#pragma unroll
            for (int mi = 0; mi < 4; mi++) {
                const uint32_t off =
                    swz((uint32_t)((wm * 64 + mi * 16 + fr) * 64 + ks * 32 + kc * 16));
                ldsm_x4(af[mi], sa + off);
            }
            uint32_t bfrag[2][4];
#pragma unroll
            for (int nj2 = 0; nj2 < 2; nj2++) {
                const uint32_t off =
                    swz((uint32_t)((wn * 32 + nj2 * 16 + fr) * 64 + ks * 32 + kc * 16));
                ldsm_x4(bfrag[nj2], sb + off);
            }
#pragma unroll
            for (int mi = 0; mi < 4; mi++)
#pragma unroll
                for (int nj = 0; nj < 4; nj++)
                    mma16816(acc[mi][nj], af[mi],
                             bfrag[nj >> 1][nj & 1], bfrag[nj >> 1][(nj & 1) + 2]);
        }
    }

    // ---- epilogue ----
    const int qr = lane >> 2;          // 0..7
    const int qc = (lane & 3) * 2;     // 0,2,4,6

    if (P3) {
        const int oi = n0 >> 10;
        float* Cp        = (oi == 0) ? (float*)ep.c0 : (oi == 1) ? (float*)ep.c1 : (float*)ep.c2;
        const float* bp  = (oi == 0) ? ep.b0 : (oi == 1) ? ep.b1 : ep.b2;
        const int nb = n0 & 1023;
#pragma unroll
        for (int mi = 0; mi < 4; mi++) {
#pragma unroll
            for (int nj = 0; nj < 4; nj++) {
                const int gm = m0 + wm * 64 + mi * 16 + qr;
                const int nn = nb + wn * 32 + nj * 8 + qc;
                const float b0 = bp[nn], b1 = bp[nn + 1];
                float* p0 = Cp + (size_t)gm * ldc + nn;
                float* p1 = Cp + (size_t)(gm + 8) * ldc + nn;
                *(float2*)p0 = make_float2(acc[mi][nj][0] + b0, acc[mi][nj][1] + b1);
                *(float2*)p1 = make_float2(acc[mi][nj][2] + b0, acc[mi][nj][3] + b1);
            }
        }
    } else if (OHALF) {
        __half* Cp = (__half*)ep.c0 + (long long)bz * sC;
#pragma unroll
        for (int mi = 0; mi < 4; mi++) {
#pragma unroll
            for (int nj = 0; nj < 4; nj++) {
                const int gm = m0 + wm * 64 + mi * 16 + qr;
                const int gn = n0 + wn * 32 + nj * 8 + qc;
                *(__half2*)(Cp + (size_t)gm * ldc + gn) =
                    __floats2half2_rn(acc[mi][nj][0], acc[mi][nj][1]);
                *(__half2*)(Cp + (size_t)(gm + 8) * ldc + gn) =
                    __floats2half2_rn(acc[mi][nj][2], acc[mi][nj][3]);
            }
        }
    } else {
        float* Cp = (float*)ep.c0 + (long long)bz * sC;
        const float sc = ep.oscale;
#pragma unroll
        for (int mi = 0; mi < 4; mi++) {
#pragma unroll
            for (int nj = 0; nj < 4; nj++) {
                const int gm = m0 + wm * 64 + mi * 16 + qr;
                const int gn = n0 + wn * 32 + nj * 8 + qc;
                *(float2*)(Cp + (size_t)gm * ldc + gn) =
                    make_float2(acc[mi][nj][0] * sc, acc[mi][nj][1] * sc);
                *(float2*)(Cp + (size_t)(gm + 8) * ldc + gn) =
                    make_float2(acc[mi][nj][2] * sc, acc[mi][nj][3] * sc);
            }
        }
    }
}

// ---------------------------------------------------------------------------
// conv_h: h fp32 [MQ,1024] -> fp16 same layout
// ---------------------------------------------------------------------------
__global__ void conv_h_kernel(const float* __restrict__ h, __half* __restrict__ hh)
{
    const size_t idx = ((size_t)blockIdx.x * 256 + threadIdx.x) * 4;
    float4 x = *(const float4*)(h + idx);
    __half o[4] = { __float2half_rn(x.x), __float2half_rn(x.y),
                    __float2half_rn(x.z), __float2half_rn(x.w) };
    *(uint2*)(hh + idx) = *(const uint2*)o;
}

// conv_w: 3 weights fp32 [1024,1024] -> stacked fp16 [3072,1024]
__global__ void conv_w_kernel(W3Args w, __half* __restrict__ w3)
{
    const size_t idx = ((size_t)blockIdx.x * 256 + threadIdx.x) * 4;  // 3*1024*1024 elems
    const int    oi  = (int)(idx >> 20);
    const size_t rem = idx & 1048575;
    const float* W = (oi == 0) ? w.w0 : (oi == 1) ? w.w1 : w.w2;
    float4 x = *(const float4*)(W + rem);
    __half o[4] = { __float2half_rn(x.x), __float2half_rn(x.y),
                    __float2half_rn(x.z), __float2half_rn(x.w) };
    *(uint2*)(w3 + (size_t)oi * 1048576 + rem) = *(const uint2*)o;
}

// ---------------------------------------------------------------------------
// Row softmax (q) over D=1024, fp32 in -> fp16 out (x256). One block per row.
// ---------------------------------------------------------------------------
__global__ void row_softmax_kernel(const float* __restrict__ x, __half* __restrict__ o)
{
    const long long row = blockIdx.x;
    const float* p = x + row * DD;
    __half* q = o + row * DD;
    const int t = threadIdx.x;

    float v[4];
#pragma unroll
    for (int i = 0; i < 4; i++) v[i] = p[t + i * 256];

    float m = fmaxf(fmaxf(v[0], v[1]), fmaxf(v[2], v[3]));
#pragma unroll
    for (int off = 16; off; off >>= 1) m = fmaxf(m, __shfl_xor_sync(0xffffffffu, m, off));

    __shared__ float redm[8], reds[8];
    if ((t & 31) == 0) redm[t >> 5] = m;
    __syncthreads();
    m = redm[0];
#pragma unroll
    for (int i = 1; i < 8; i++) m = fmaxf(m, redm[i]);

    float s = 0.f;
#pragma unroll
    for (int i = 0; i < 4; i++) { v[i] = __expf(v[i] - m); s += v[i]; }
#pragma unroll
    for (int off = 16; off; off >>= 1) s += __shfl_xor_sync(0xffffffffu, s, off);
    if ((t & 31) == 0) reds[t >> 5] = s;
    __syncthreads();
    s = 0.f;
#pragma unroll
    for (int i = 0; i < 8; i++) s += reds[i];
    const float inv = PROB_SCALE / s;
#pragma unroll
    for (int i = 0; i < 4; i++) q[t + i * 256] = __float2half_rn(v[i] * inv);
}

// ---------------------------------------------------------------------------
// Column softmax over S=4096 (x256), fused transpose + fp16:
//   in : fp32 [S, D] (per batch), out : fp16 [D, S] (per batch)
// grid (D/32, B), block (32, 8).
// ---------------------------------------------------------------------------
__global__ void col_softmaxT_kernel(const float* __restrict__ x, __half* __restrict__ xT)
{
    const int tx = threadIdx.x;
    const int ty = threadIdx.y;
    const int d0 = blockIdx.x * 32;
    const float* base = x + (long long)blockIdx.y * SS * DD;
    __half* ob = xT + (long long)blockIdx.y * DD * SS + (long long)d0 * SS;
    const float* p = base + d0 + tx;

    float m = -3.4e38f, s = 0.f;
    for (int r = ty; r < SS; r += 8) {
        const float xv = p[(long long)r * DD];
        if (xv > m) { s *= __expf(m - xv); m = xv; }
        s += __expf(xv - m);
    }
    __shared__ float sm[8][32], ssum[8][32];
    sm[ty][tx] = m; ssum[ty][tx] = s;
    __syncthreads();
    __shared__ float colM[32], colR[32];
    if (ty == 0) {
        float M = sm[0][tx];
#pragma unroll
        for (int i = 1; i < 8; i++) M = fmaxf(M, sm[i][tx]);
        float T = 0.f;
#pragma unroll
        for (int i = 0; i < 8; i++) T += ssum[i][tx] * __expf(sm[i][tx] - M);
        colM[tx] = M; colR[tx] = PROB_SCALE / T;
    }
    __syncthreads();
    const float M = colM[tx];
    const float R = colR[tx];

    __shared__ float tile[32][33];
    for (int s0 = 0; s0 < SS; s0 += 32) {
#pragma unroll
        for (int j = 0; j < 4; j++) {
            const int sl = ty + 8 * j;
            tile[sl][tx] = __expf(p[(long long)(s0 + sl) * DD] - M) * R;
        }
        __syncthreads();
#pragma unroll
        for (int j = 0; j < 4; j++) {
            const int dl = ty + 8 * j;
            ob[(long long)dl * SS + s0 + tx] = __float2half_rn(tile[tx][dl]);
        }
        __syncthreads();
    }
}

// ---------------------------------------------------------------------------
// launch
// ---------------------------------------------------------------------------
extern "C" void kernel_launch(void* const* d_in, const int* in_sizes, int n_in,
                              void* d_out, int out_size)
{
    const float* h  = (const float*)d_in[0];
    const float* Wq = (const float*)d_in[1];
    const float* bq = (const float*)d_in[2];
    const float* Wk = (const float*)d_in[3];
    const float* bk = (const float*)d_in[4];
    const float* Wv = (const float*)d_in[5];
    const float* bv = (const float*)d_in[6];
    float* out = (float*)d_out;

    float *q, *k, *v;
    __half *hh, *w3, *qb, *kT, *vT, *kvt;
    cudaGetSymbolAddress((void**)&q,   g_q);
    cudaGetSymbolAddress((void**)&k,   g_k);
    cudaGetSymbolAddress((void**)&v,   g_v);
    cudaGetSymbolAddress((void**)&hh,  g_hh);
    cudaGetSymbolAddress((void**)&w3,  g_w3);
    cudaGetSymbolAddress((void**)&qb,  g_qb);
    cudaGetSymbolAddress((void**)&kT,  g_kT);
    cudaGetSymbolAddress((void**)&vT,  g_vT);
    cudaGetSymbolAddress((void**)&kvt, g_kvt);

    // 1) fp16 conversions
    conv_h_kernel<<<MQ * DD / 1024, 256>>>(h, hh);
    W3Args wa{ Wq, Wk, Wv };
    conv_w_kernel<<<3 * DD * DD / 1024, 256>>>(wa, w3);

    // 2) fused projection GEMM: [16384, 3072] = h @ [Wq;Wk;Wv]^T, K=1024
    //    output cols [0,1024)->q, [1024,2048)->k, [2048,3072)->v (fp32 + bias)
    {
        EpiArgs ep{ q, k, v, bq, bk, bv, 1.0f };
        gemm_mma<true, false><<<dim3(24, 128, 1), 256>>>(
            hh, DD, w3, DD, ep, DD, DD, 0, 0, 0);
    }

    // 3) softmaxes (fused convert / transpose to fp16, x256 range scaling)
    row_softmax_kernel<<<MQ, 256>>>(q, qb);
    col_softmaxT_kernel<<<dim3(DD / 32, BB), dim3(32, 8)>>>(k, kT);
    col_softmaxT_kernel<<<dim3(DD / 32, BB), dim3(32, 8)>>>(v, vT);

    // 4) kvt'[b][a,c] = sum_s vT[b][a,s] * kT[b][c,s]  (M=N=1024, K=4096, fp16 out)
    {
        EpiArgs ep{ kvt, nullptr, nullptr, nullptr, nullptr, nullptr, 1.0f };
        gemm_mma<false, true><<<dim3(8, 8, BB), 256>>>(
            vT, SS, kT, SS, ep, DD, SS,
            (long long)DD * SS, (long long)DD * SS, (long long)DD * DD);
    }

    // 5) out[b] = qb[b] @ kvt'[b]^T * 2^-29  (K=1024)
    {
        EpiArgs ep{ out, nullptr, nullptr, nullptr, nullptr, nullptr, OUT_SCALE };
        gemm_mma<false, false><<<dim3(8, 32, BB), 256>>>(
            qb, DD, kvt, DD, ep, DD, DD,
            (long long)SS * DD, (long long)DD * DD, (long long)SS * DD);
    }
}